// round 4
// baseline (speedup 1.0000x reference)
#include <cuda_runtime.h>
#include <math.h>

// Problem constants
#define T_    4
#define HH    256
#define WW    256
#define C_    256
#define PS_   8
#define NH_   8
#define HD_   32
#define NTOK  64          // PS*PS tokens per window
#define NWIN  4096        // 4 * 32 * 32 windows
#define SCALE 0.1767766952966369f   // 1/sqrt(32)

// ---------------------------------------------------------------------------
// Scratch (allocation-free rule: __device__ globals)
// Q/K/V laid out [win][head][tok][dim] for the attention kernel.
// g_att laid out [win*64 + tok][256] (row-major for proj GEMM).
// ---------------------------------------------------------------------------
__device__ float g_q[(size_t)NWIN * NH_ * NTOK * HD_];
__device__ float g_k[(size_t)NWIN * NH_ * NTOK * HD_];
__device__ float g_v[(size_t)NWIN * NH_ * NTOK * HD_];
__device__ float g_att[(size_t)NWIN * NTOK * C_];

// ---------------------------------------------------------------------------
// Kernel 1: fused windowize + modulator + QKV GEMM
//   rows  = 64 tokens of one window (A tile gathered from vid + modulator)
//   cols  = 768 (wq 0..255 | wkv-K 256..511 | wkv-V 512..767), BN=128 tiles
//   Epilogue scatters into g_q (scaled), g_k, g_v in per-head layout.
// ---------------------------------------------------------------------------
#define BM 64
#define BN 128
#define BK 16

__global__ __launch_bounds__(256)
void qkv_kernel(const float* __restrict__ vid, const float* __restrict__ mod,
                const float* __restrict__ wq,  const float* __restrict__ bq,
                const float* __restrict__ wkv, const float* __restrict__ bkv)
{
    __shared__ float As[BM][BK + 1];
    __shared__ float Bs[BK][BN];

    const int w   = blockIdx.y;
    const int jb0 = blockIdx.x * BN;           // 0,128,...,640
    const int t   = threadIdx.x;
    const int tx  = t & 31;                    // 0..31  -> 4 cols each
    const int ty  = t >> 5;                    // 0..7   -> 8 rows each

    // window decode for the A gather
    const int tf = w >> 10;
    const int wh = (w >> 5) & 31;
    const int wc = w & 31;

    const int aRow = t >> 2;                   // token n (0..63)
    const int aC4  = (t & 3) << 2;             // k offset within BK
    const int pi = aRow >> 3, pj = aRow & 7;
    const float* vidrow = vid + ((size_t)((tf * HH + wh * PS_ + pi)) * WW
                                 + (wc * PS_ + pj)) * C_;
    const float* modrow = mod + aRow * C_;

    // B source selection (tile never straddles the 256-col boundaries)
    const float* bsrc; int ldb, jcol0;
    if (jb0 < C_) { bsrc = wq;  ldb = C_;     jcol0 = jb0; }
    else          { bsrc = wkv; ldb = 2 * C_; jcol0 = jb0 - C_; }

    float acc[8][4];
    #pragma unroll
    for (int i = 0; i < 8; i++)
        #pragma unroll
        for (int j = 0; j < 4; j++) acc[i][j] = 0.f;

    for (int k0 = 0; k0 < C_; k0 += BK) {
        // A tile: vid + modulator (coalesced float4 along C)
        float4 va = *(const float4*)(vidrow + k0 + aC4);
        float4 vm = *(const float4*)(modrow + k0 + aC4);
        As[aRow][aC4 + 0] = va.x + vm.x;
        As[aRow][aC4 + 1] = va.y + vm.y;
        As[aRow][aC4 + 2] = va.z + vm.z;
        As[aRow][aC4 + 3] = va.w + vm.w;
        // B tile: 2 float4 per thread
        #pragma unroll
        for (int p = 0; p < 2; p++) {
            int f    = t + p * 256;
            int bRow = f >> 5;
            int bC4  = (f & 31) << 2;
            *(float4*)&Bs[bRow][bC4] =
                *(const float4*)(bsrc + (size_t)(k0 + bRow) * ldb + jcol0 + bC4);
        }
        __syncthreads();

        #pragma unroll
        for (int kk = 0; kk < BK; kk++) {
            float ra[8];
            #pragma unroll
            for (int i = 0; i < 8; i++) ra[i] = As[ty * 8 + i][kk];
            float4 b4 = *(float4*)&Bs[kk][tx * 4];
            float rb[4] = {b4.x, b4.y, b4.z, b4.w};
            #pragma unroll
            for (int i = 0; i < 8; i++)
                #pragma unroll
                for (int j = 0; j < 4; j++)
                    acc[i][j] += ra[i] * rb[j];
        }
        __syncthreads();
    }

    // Epilogue: bias, scale (Q only), scatter to per-head layout
    const int jg0 = jb0 + tx * 4;              // global output col (4 consecutive)
    float bias4[4];
    float* dst;
    int   jloc0;
    float mul;
    if (jb0 < C_) {                            // Q
        #pragma unroll
        for (int j = 0; j < 4; j++) bias4[j] = bq[jg0 + j];
        dst = g_q; jloc0 = jg0; mul = SCALE;
    } else if (jb0 < 2 * C_) {                 // K
        #pragma unroll
        for (int j = 0; j < 4; j++) bias4[j] = bkv[jg0 - C_ + j];
        dst = g_k; jloc0 = jg0 - C_; mul = 1.f;
    } else {                                   // V
        #pragma unroll
        for (int j = 0; j < 4; j++) bias4[j] = bkv[jg0 - C_ + j];
        dst = g_v; jloc0 = jg0 - 2 * C_; mul = 1.f;
    }
    const int h = jloc0 >> 5;                  // head (4 cols stay in one head)
    const int d = jloc0 & 31;
    #pragma unroll
    for (int i = 0; i < 8; i++) {
        int n = ty * 8 + i;
        float4 o;
        o.x = (acc[i][0] + bias4[0]) * mul;
        o.y = (acc[i][1] + bias4[1]) * mul;
        o.z = (acc[i][2] + bias4[2]) * mul;
        o.w = (acc[i][3] + bias4[3]) * mul;
        *(float4*)&dst[(((size_t)w * NH_ + h) * NTOK + n) * HD_ + d] = o;
    }
}

// ---------------------------------------------------------------------------
// Kernel 2: per-window attention. Block = (window, 2 heads), 128 threads.
// Thread = one query row of one head: full 64-score softmax in registers.
// ---------------------------------------------------------------------------
__global__ __launch_bounds__(128)
void attn_kernel(const float* __restrict__ rpt)
{
    __shared__ float Ks[2][NTOK][HD_];
    __shared__ float Vs[2][NTOK][HD_];
    __shared__ float tb[2][225];

    const int w  = blockIdx.x;
    const int hl = threadIdx.x >> 6;           // 0/1 within block
    const int n  = threadIdx.x & 63;           // query token
    const int h  = blockIdx.y * 2 + hl;

    const size_t base = ((size_t)w * NH_ + h) * NTOK * HD_;

    #pragma unroll
    for (int d4 = 0; d4 < HD_; d4 += 4) {
        *(float4*)&Ks[hl][n][d4] = *(const float4*)&g_k[base + n * HD_ + d4];
        *(float4*)&Vs[hl][n][d4] = *(const float4*)&g_v[base + n * HD_ + d4];
    }
    for (int i = n; i < 225; i += 64) tb[hl][i] = rpt[i * NH_ + h];

    float qr[HD_];
    #pragma unroll
    for (int d4 = 0; d4 < HD_; d4 += 4) {
        float4 q4 = *(const float4*)&g_q[base + n * HD_ + d4];
        qr[d4] = q4.x; qr[d4+1] = q4.y; qr[d4+2] = q4.z; qr[d4+3] = q4.w;
    }
    __syncthreads();

    const int qi = n >> 3, qj = n & 7;
    float s[NTOK];
    float mx = -1e30f;
    #pragma unroll
    for (int k = 0; k < NTOK; k++) {
        float dot = 0.f;
        #pragma unroll
        for (int d = 0; d < HD_; d++) dot += qr[d] * Ks[hl][k][d];
        const int ki = k >> 3, kj = k & 7;
        dot += tb[hl][(qi - ki + 7) * 15 + (qj - kj + 7)];
        s[k] = dot;
        mx = fmaxf(mx, dot);
    }
    float sum = 0.f;
    #pragma unroll
    for (int k = 0; k < NTOK; k++) { float e = __expf(s[k] - mx); s[k] = e; sum += e; }
    const float inv = 1.f / sum;

    float o[HD_];
    #pragma unroll
    for (int d = 0; d < HD_; d++) o[d] = 0.f;
    #pragma unroll
    for (int k = 0; k < NTOK; k++) {
        float wgt = s[k];
        #pragma unroll
        for (int d = 0; d < HD_; d++) o[d] += wgt * Vs[hl][k][d];
    }

    float* dstp = g_att + ((size_t)w * NTOK + n) * C_ + h * HD_;
    #pragma unroll
    for (int d4 = 0; d4 < HD_; d4 += 4) {
        float4 o4 = {o[d4] * inv, o[d4+1] * inv, o[d4+2] * inv, o[d4+3] * inv};
        *(float4*)&dstp[d4] = o4;
    }
}

// ---------------------------------------------------------------------------
// Kernel 3: output projection + un-windowize, fused.
// ---------------------------------------------------------------------------
__global__ __launch_bounds__(256)
void proj_kernel(const float* __restrict__ pw, const float* __restrict__ pb,
                 float* __restrict__ out)
{
    __shared__ float As[BM][BK + 1];
    __shared__ float Bs[BK][BN];

    const int w   = blockIdx.y;
    const int jb0 = blockIdx.x * BN;           // 0 or 128
    const int t   = threadIdx.x;
    const int tx  = t & 31;
    const int ty  = t >> 5;

    const int aRow = t >> 2;
    const int aC4  = (t & 3) << 2;
    const float* arow = g_att + ((size_t)w * NTOK + aRow) * C_;

    float acc[8][4];
    #pragma unroll
    for (int i = 0; i < 8; i++)
        #pragma unroll
        for (int j = 0; j < 4; j++) acc[i][j] = 0.f;

    for (int k0 = 0; k0 < C_; k0 += BK) {
        float4 va = *(const float4*)(arow + k0 + aC4);
        As[aRow][aC4 + 0] = va.x;
        As[aRow][aC4 + 1] = va.y;
        As[aRow][aC4 + 2] = va.z;
        As[aRow][aC4 + 3] = va.w;
        #pragma unroll
        for (int p = 0; p < 2; p++) {
            int f    = t + p * 256;
            int bRow = f >> 5;
            int bC4  = (f & 31) << 2;
            *(float4*)&Bs[bRow][bC4] =
                *(const float4*)(pw + (size_t)(k0 + bRow) * C_ + jb0 + bC4);
        }
        __syncthreads();
        #pragma unroll
        for (int kk = 0; kk < BK; kk++) {
            float ra[8];
            #pragma unroll
            for (int i = 0; i < 8; i++) ra[i] = As[ty * 8 + i][kk];
            float4 b4 = *(float4*)&Bs[kk][tx * 4];
            float rb[4] = {b4.x, b4.y, b4.z, b4.w};
            #pragma unroll
            for (int i = 0; i < 8; i++)
                #pragma unroll
                for (int j = 0; j < 4; j++)
                    acc[i][j] += ra[i] * rb[j];
        }
        __syncthreads();
    }

    // window -> spatial scatter
    const int tf = w >> 10;
    const int wh = (w >> 5) & 31;
    const int wc = w & 31;
    const int jg = jb0 + tx * 4;
    float bias4[4];
    #pragma unroll
    for (int j = 0; j < 4; j++) bias4[j] = pb[jg + j];

    #pragma unroll
    for (int i = 0; i < 8; i++) {
        int n  = ty * 8 + i;
        int pi = n >> 3, pj = n & 7;
        float* orow = out + ((size_t)((tf * HH + wh * PS_ + pi)) * WW
                             + (wc * PS_ + pj)) * C_;
        float4 o;
        o.x = acc[i][0] + bias4[0];
        o.y = acc[i][1] + bias4[1];
        o.z = acc[i][2] + bias4[2];
        o.w = acc[i][3] + bias4[3];
        *(float4*)&orow[jg] = o;
    }
}

// ---------------------------------------------------------------------------
extern "C" void kernel_launch(void* const* d_in, const int* in_sizes, int n_in,
                              void* d_out, int out_size)
{
    const float* vid  = (const float*)d_in[0];
    const float* mod  = (const float*)d_in[1];
    const float* wq   = (const float*)d_in[2];
    const float* bq   = (const float*)d_in[3];
    const float* wkv  = (const float*)d_in[4];
    const float* bkv  = (const float*)d_in[5];
    const float* pw   = (const float*)d_in[6];
    const float* pb   = (const float*)d_in[7];
    const float* rpt  = (const float*)d_in[8];
    float* out = (float*)d_out;

    dim3 g1(6, NWIN);
    qkv_kernel<<<g1, 256>>>(vid, mod, wq, bq, wkv, bkv);

    dim3 g2(NWIN, NH_ / 2);
    attn_kernel<<<g2, 128>>>(rpt);

    dim3 g3(2, NWIN);
    proj_kernel<<<g3, 256>>>(pw, pb, out);
}

// round 6
// speedup vs baseline: 1.9666x; 1.9666x over previous
#include <cuda_runtime.h>
#include <math.h>

// Problem constants
#define T_    4
#define HH    256
#define WW    256
#define C_    256
#define PS_   8
#define NH_   8
#define HD_   32
#define NTOK  64
#define NWIN  4096
#define SCALE 0.1767766952966369f   // 1/sqrt(32)

// ---------------------------------------------------------------------------
// Scratch (__device__ globals: allocation-free rule)
// ---------------------------------------------------------------------------
__device__ float g_q[(size_t)NWIN * NH_ * NTOK * HD_];
__device__ float g_k[(size_t)NWIN * NH_ * NTOK * HD_];
__device__ float g_v[(size_t)NWIN * NH_ * NTOK * HD_];
__device__ float g_att[(size_t)NWIN * NTOK * C_];

// ---------------------------------------------------------------------------
// tf32 helpers
// ---------------------------------------------------------------------------
__device__ __forceinline__ float to_tf32(float x) {
    float r;
    asm("cvt.rna.tf32.f32 %0, %1;" : "=f"(r) : "f"(x));
    return r;
}

__device__ __forceinline__ void mma_tf32(float c[4],
                                         unsigned a0, unsigned a1, unsigned a2, unsigned a3,
                                         unsigned b0, unsigned b1) {
    asm volatile(
        "mma.sync.aligned.m16n8k8.row.col.f32.tf32.tf32.f32 "
        "{%0,%1,%2,%3}, {%4,%5,%6,%7}, {%8,%9}, {%0,%1,%2,%3};"
        : "+f"(c[0]), "+f"(c[1]), "+f"(c[2]), "+f"(c[3])
        : "r"(a0), "r"(a1), "r"(a2), "r"(a3), "r"(b0), "r"(b1));
}

// Tile geometry (shared by both GEMM kernels)
#define BM 64
#define BN 128
#define BK 32
#define SA 36     // A smem stride (floats): (4*grp+qid)%32 conflict-free
#define SB 136    // B smem stride (floats): (8*qid+grp)%32 conflict-free

// ---------------------------------------------------------------------------
// Kernel 1: fused windowize + modulator + QKV GEMM (tf32 tensor cores)
//   grid (6, NWIN), block 256 (8 warps, 2x4 warp grid, warp tile 32x32)
// ---------------------------------------------------------------------------
__global__ __launch_bounds__(256)
void qkv_kernel(const float* __restrict__ vid, const float* __restrict__ mod,
                const float* __restrict__ wq,  const float* __restrict__ bq,
                const float* __restrict__ wkv, const float* __restrict__ bkv)
{
    __shared__ float As[BM * SA];
    __shared__ float Bs[BK * SB];

    const int w   = blockIdx.y;
    const int jb0 = blockIdx.x * BN;
    const int t   = threadIdx.x;
    const int warp   = t >> 5;
    const int lane   = t & 31;
    const int grp    = lane >> 2;      // 0..7
    const int qid    = lane & 3;       // 0..3
    const int warp_m = warp >> 2;      // 0..1
    const int warp_n = warp & 3;       // 0..3

    // window decode
    const int tf = w >> 10;
    const int wh = (w >> 5) & 31;
    const int wc = w & 31;

    // B source (tile never straddles 256-col boundaries)
    const float* bsrc; int ldb, jcol0;
    if (jb0 < C_) { bsrc = wq;  ldb = C_;     jcol0 = jb0; }
    else          { bsrc = wkv; ldb = 2 * C_; jcol0 = jb0 - C_; }

    // A-load coords: thread loads rows t/8 and t/8+32, cols (t&7)*4..+3
    const int arow0 = t >> 3;
    const int acol  = (t & 7) << 2;
    // B-load coords: row t/32 + 8*pass, cols (t&31)*4
    const int brow0 = t >> 5;
    const int bcol  = (t & 31) << 2;

    float acc[2][4][4];
    #pragma unroll
    for (int mt = 0; mt < 2; mt++)
        #pragma unroll
        for (int nt = 0; nt < 4; nt++)
            #pragma unroll
            for (int i = 0; i < 4; i++) acc[mt][nt][i] = 0.f;

    for (int k0 = 0; k0 < C_; k0 += BK) {
        // ---- A tile: vid + modulator, tf32-rounded ----
        #pragma unroll
        for (int pass = 0; pass < 2; pass++) {
            int row = arow0 + pass * 32;
            int pi = row >> 3, pj = row & 7;
            const float* src = vid + ((size_t)(tf * HH + wh * PS_ + pi) * WW
                                      + wc * PS_ + pj) * C_ + k0 + acol;
            float4 va = *(const float4*)src;
            float4 vm = *(const float4*)(mod + row * C_ + k0 + acol);
            float* d = &As[row * SA + acol];
            d[0] = to_tf32(va.x + vm.x);
            d[1] = to_tf32(va.y + vm.y);
            d[2] = to_tf32(va.z + vm.z);
            d[3] = to_tf32(va.w + vm.w);
        }
        // ---- B tile ----
        #pragma unroll
        for (int pass = 0; pass < 4; pass++) {
            int row = brow0 + pass * 8;
            float4 b4 = *(const float4*)(bsrc + (size_t)(k0 + row) * ldb + jcol0 + bcol);
            float* d = &Bs[row * SB + bcol];
            d[0] = to_tf32(b4.x);
            d[1] = to_tf32(b4.y);
            d[2] = to_tf32(b4.z);
            d[3] = to_tf32(b4.w);
        }
        __syncthreads();

        #pragma unroll
        for (int kk = 0; kk < BK; kk += 8) {
            unsigned a[2][4];
            #pragma unroll
            for (int mt = 0; mt < 2; mt++) {
                int rb = warp_m * 32 + mt * 16;
                a[mt][0] = __float_as_uint(As[(rb + grp    ) * SA + kk + qid    ]);
                a[mt][1] = __float_as_uint(As[(rb + grp + 8) * SA + kk + qid    ]);
                a[mt][2] = __float_as_uint(As[(rb + grp    ) * SA + kk + qid + 4]);
                a[mt][3] = __float_as_uint(As[(rb + grp + 8) * SA + kk + qid + 4]);
            }
            unsigned b[4][2];
            #pragma unroll
            for (int nt = 0; nt < 4; nt++) {
                int cb = warp_n * 32 + nt * 8;
                b[nt][0] = __float_as_uint(Bs[(kk + qid    ) * SB + cb + grp]);
                b[nt][1] = __float_as_uint(Bs[(kk + qid + 4) * SB + cb + grp]);
            }
            #pragma unroll
            for (int mt = 0; mt < 2; mt++)
                #pragma unroll
                for (int nt = 0; nt < 4; nt++)
                    mma_tf32(acc[mt][nt], a[mt][0], a[mt][1], a[mt][2], a[mt][3],
                             b[nt][0], b[nt][1]);
        }
        __syncthreads();
    }

    // ---- Epilogue: bias + scale + per-head scatter ----
    float* dst; int secoff; float mul;
    const float* bias_src;
    if (jb0 < C_)            { dst = g_q; secoff = 0;      mul = SCALE; bias_src = bq; }
    else if (jb0 < 2 * C_)   { dst = g_k; secoff = C_;     mul = 1.f;   bias_src = bkv; }
    else                     { dst = g_v; secoff = 2 * C_; mul = 1.f;   bias_src = bkv - C_; }
    // bias index: for K/V, bias = bkv[jglobal - 256] handled via bias_src offset:
    //   K: jg-256 -> bkv + (jg - 256) = bias_src + jg - C_ ... simplify below.

    #pragma unroll
    for (int nt = 0; nt < 4; nt++) {
        int col  = jb0 + warp_n * 32 + nt * 8 + 2 * qid;  // global QKV col
        int jloc = col - secoff;                           // 0..255 within section
        float b0, b1;
        if (jb0 < C_) { b0 = bq[col];       b1 = bq[col + 1]; }
        else          { b0 = bkv[col - C_]; b1 = bkv[col + 1 - C_]; }
        int h = jloc >> 5;
        int d = jloc & 31;
        float* hp = dst + (((size_t)w * NH_ + h) * NTOK) * HD_ + d;
        #pragma unroll
        for (int mt = 0; mt < 2; mt++) {
            int m0 = warp_m * 32 + mt * 16 + grp;
            float2 o0 = { (acc[mt][nt][0] + b0) * mul, (acc[mt][nt][1] + b1) * mul };
            float2 o1 = { (acc[mt][nt][2] + b0) * mul, (acc[mt][nt][3] + b1) * mul };
            *(float2*)(hp + (size_t)m0 * HD_)       = o0;
            *(float2*)(hp + (size_t)(m0 + 8) * HD_) = o1;
        }
    }
}

// ---------------------------------------------------------------------------
// Kernel 2: per-window attention (SIMT, unchanged from baseline)
// ---------------------------------------------------------------------------
__global__ __launch_bounds__(128)
void attn_kernel(const float* __restrict__ rpt)
{
    __shared__ float Ks[2][NTOK][HD_];
    __shared__ float Vs[2][NTOK][HD_];
    __shared__ float tb[2][225];

    const int w  = blockIdx.x;
    const int hl = threadIdx.x >> 6;
    const int n  = threadIdx.x & 63;
    const int h  = blockIdx.y * 2 + hl;

    const size_t base = ((size_t)w * NH_ + h) * NTOK * HD_;

    #pragma unroll
    for (int d4 = 0; d4 < HD_; d4 += 4) {
        *(float4*)&Ks[hl][n][d4] = *(const float4*)&g_k[base + n * HD_ + d4];
        *(float4*)&Vs[hl][n][d4] = *(const float4*)&g_v[base + n * HD_ + d4];
    }
    for (int i = n; i < 225; i += 64) tb[hl][i] = rpt[i * NH_ + h];

    float qr[HD_];
    #pragma unroll
    for (int d4 = 0; d4 < HD_; d4 += 4) {
        float4 q4 = *(const float4*)&g_q[base + n * HD_ + d4];
        qr[d4] = q4.x; qr[d4+1] = q4.y; qr[d4+2] = q4.z; qr[d4+3] = q4.w;
    }
    __syncthreads();

    const int qi = n >> 3, qj = n & 7;
    float s[NTOK];
    float mx = -1e30f;
    #pragma unroll
    for (int k = 0; k < NTOK; k++) {
        float dot = 0.f;
        #pragma unroll
        for (int d = 0; d < HD_; d++) dot += qr[d] * Ks[hl][k][d];
        const int ki = k >> 3, kj = k & 7;
        dot += tb[hl][(qi - ki + 7) * 15 + (qj - kj + 7)];
        s[k] = dot;
        mx = fmaxf(mx, dot);
    }
    float sum = 0.f;
    #pragma unroll
    for (int k = 0; k < NTOK; k++) { float e = __expf(s[k] - mx); s[k] = e; sum += e; }
    const float inv = 1.f / sum;

    float o[HD_];
    #pragma unroll
    for (int d = 0; d < HD_; d++) o[d] = 0.f;
    #pragma unroll
    for (int k = 0; k < NTOK; k++) {
        float wgt = s[k];
        #pragma unroll
        for (int d = 0; d < HD_; d++) o[d] += wgt * Vs[hl][k][d];
    }

    float* dstp = g_att + ((size_t)w * NTOK + n) * C_ + h * HD_;
    #pragma unroll
    for (int d4 = 0; d4 < HD_; d4 += 4) {
        float4 o4 = {o[d4] * inv, o[d4+1] * inv, o[d4+2] * inv, o[d4+3] * inv};
        *(float4*)&dstp[d4] = o4;
    }
}

// ---------------------------------------------------------------------------
// Kernel 3: output projection + un-windowize (tf32 tensor cores)
//   grid (2, NWIN), block 256
// ---------------------------------------------------------------------------
__global__ __launch_bounds__(256)
void proj_kernel(const float* __restrict__ pw, const float* __restrict__ pb,
                 float* __restrict__ out)
{
    __shared__ float As[BM * SA];
    __shared__ float Bs[BK * SB];

    const int w   = blockIdx.y;
    const int jb0 = blockIdx.x * BN;
    const int t   = threadIdx.x;
    const int warp   = t >> 5;
    const int lane   = t & 31;
    const int grp    = lane >> 2;
    const int qid    = lane & 3;
    const int warp_m = warp >> 2;
    const int warp_n = warp & 3;

    const int arow0 = t >> 3;
    const int acol  = (t & 7) << 2;
    const int brow0 = t >> 5;
    const int bcol  = (t & 31) << 2;

    float acc[2][4][4];
    #pragma unroll
    for (int mt = 0; mt < 2; mt++)
        #pragma unroll
        for (int nt = 0; nt < 4; nt++)
            #pragma unroll
            for (int i = 0; i < 4; i++) acc[mt][nt][i] = 0.f;

    for (int k0 = 0; k0 < C_; k0 += BK) {
        #pragma unroll
        for (int pass = 0; pass < 2; pass++) {
            int row = arow0 + pass * 32;
            float4 va = *(const float4*)(g_att + ((size_t)w * NTOK + row) * C_ + k0 + acol);
            float* d = &As[row * SA + acol];
            d[0] = to_tf32(va.x);
            d[1] = to_tf32(va.y);
            d[2] = to_tf32(va.z);
            d[3] = to_tf32(va.w);
        }
        #pragma unroll
        for (int pass = 0; pass < 4; pass++) {
            int row = brow0 + pass * 8;
            float4 b4 = *(const float4*)(pw + (size_t)(k0 + row) * C_ + jb0 + bcol);
            float* d = &Bs[row * SB + bcol];
            d[0] = to_tf32(b4.x);
            d[1] = to_tf32(b4.y);
            d[2] = to_tf32(b4.z);
            d[3] = to_tf32(b4.w);
        }
        __syncthreads();

        #pragma unroll
        for (int kk = 0; kk < BK; kk += 8) {
            unsigned a[2][4];
            #pragma unroll
            for (int mt = 0; mt < 2; mt++) {
                int rb = warp_m * 32 + mt * 16;
                a[mt][0] = __float_as_uint(As[(rb + grp    ) * SA + kk + qid    ]);
                a[mt][1] = __float_as_uint(As[(rb + grp + 8) * SA + kk + qid    ]);
                a[mt][2] = __float_as_uint(As[(rb + grp    ) * SA + kk + qid + 4]);
                a[mt][3] = __float_as_uint(As[(rb + grp + 8) * SA + kk + qid + 4]);
            }
            unsigned b[4][2];
            #pragma unroll
            for (int nt = 0; nt < 4; nt++) {
                int cb = warp_n * 32 + nt * 8;
                b[nt][0] = __float_as_uint(Bs[(kk + qid    ) * SB + cb + grp]);
                b[nt][1] = __float_as_uint(Bs[(kk + qid + 4) * SB + cb + grp]);
            }
            #pragma unroll
            for (int mt = 0; mt < 2; mt++)
                #pragma unroll
                for (int nt = 0; nt < 4; nt++)
                    mma_tf32(acc[mt][nt], a[mt][0], a[mt][1], a[mt][2], a[mt][3],
                             b[nt][0], b[nt][1]);
        }
        __syncthreads();
    }

    // ---- Epilogue: bias + spatial scatter ----
    const int tf = w >> 10;
    const int wh = (w >> 5) & 31;
    const int wc = w & 31;

    #pragma unroll
    for (int nt = 0; nt < 4; nt++) {
        int col = jb0 + warp_n * 32 + nt * 8 + 2 * qid;
        float b0 = pb[col], b1 = pb[col + 1];
        #pragma unroll
        for (int mt = 0; mt < 2; mt++) {
            #pragma unroll
            for (int half = 0; half < 2; half++) {
                int m  = warp_m * 32 + mt * 16 + grp + half * 8;
                int pi = m >> 3, pj = m & 7;
                float* orow = out + ((size_t)(tf * HH + wh * PS_ + pi) * WW
                                     + wc * PS_ + pj) * C_;
                float2 o = { acc[mt][nt][half * 2 + 0] + b0,
                             acc[mt][nt][half * 2 + 1] + b1 };
                *(float2*)(orow + col) = o;
            }
        }
    }
}

// ---------------------------------------------------------------------------
extern "C" void kernel_launch(void* const* d_in, const int* in_sizes, int n_in,
                              void* d_out, int out_size)
{
    const float* vid  = (const float*)d_in[0];
    const float* mod  = (const float*)d_in[1];
    const float* wq   = (const float*)d_in[2];
    const float* bq   = (const float*)d_in[3];
    const float* wkv  = (const float*)d_in[4];
    const float* bkv  = (const float*)d_in[5];
    const float* pw   = (const float*)d_in[6];
    const float* pb   = (const float*)d_in[7];
    const float* rpt  = (const float*)d_in[8];
    float* out = (float*)d_out;

    dim3 g1(6, NWIN);
    qkv_kernel<<<g1, 256>>>(vid, mod, wq, bq, wkv, bkv);

    dim3 g2(NWIN, NH_ / 2);
    attn_kernel<<<g2, 128>>>(rpt);

    dim3 g3(2, NWIN);
    proj_kernel<<<g3, 256>>>(pw, pb, out);
}